// round 15
// baseline (speedup 1.0000x reference)
#include <cuda_runtime.h>
#include <cuda_bf16.h>
#include <cstdint>

// Problem constants (fixed by dataset)
#define NE 64      // experts
#define HH 2048    // hidden dim
#define FF 1408    // intermediate dim
#define MT 16      // tokens per expert
#define KT 64      // K tile (smem)
#define XSS 10     // ull stride per k-row in x tile (8 m-pairs + 2 pad)
#define NA_PER_E (FF / 128)   // 11 A-CTAs per expert
#define NB_PER_E (HH / 128)   // 16 B-CTAs per expert
#define NA_TOT (NE * NA_PER_E)  // 704
#define NB_TOT (NE * NB_PER_E)  // 1024

typedef unsigned long long ull;

// Scratch for intermediate SwiGLU activations: [E][MT][FF] fp32 = 5.77 MB
__device__ float g_inter[(size_t)NE * MT * FF];
// Per-expert dependency counters (zero-initialized at module load; the last
// B-CTA of each expert resets them, so every launch/replay starts from 0).
__device__ int g_done[NE];
__device__ int g_bdone[NE];

// ---------- packed fp32x2 helpers (ptxas never emits FFMA2 from C++) ----------
__device__ __forceinline__ ull fma2(ull a, ull b, ull c) {
    ull d;
    asm("fma.rn.f32x2 %0, %1, %2, %3;" : "=l"(d) : "l"(a), "l"(b), "l"(c));
    return d;
}
__device__ __forceinline__ ull pack2(float lo, float hi) {
    ull d;
    asm("mov.b64 %0, {%1, %2};" : "=l"(d) : "f"(lo), "f"(hi));
    return d;
}
__device__ __forceinline__ ull dup2(float v) {
    ull d;
    asm("mov.b64 %0, {%1, %1};" : "=l"(d) : "f"(v));
    return d;
}
__device__ __forceinline__ float2 unpk(ull v) {
    float lo, hi;
    asm("mov.b64 {%0, %1}, %2;" : "=f"(lo), "=f"(hi) : "l"(v));
    return make_float2(lo, hi);
}
__device__ __forceinline__ float silu(float g) {
    return g * (1.0f / (1.0f + __expf(-g)));
}

// ============================================================================
// Fused MoE kernel: one 1D grid of 704 (gate/up proj) + 1024 (down proj) CTAs.
//  - bids [0, 704):    A role — inter[e] = silu(X_e@gate_e) * (X_e@up_e)
//                      (expert-major: expert e owns bids e*11..e*11+10)
//  - bids [704, 1728): B role — out[e] = inter_e @ down_e
//                      gated on g_done[e] == 11 (acquire spin, nanosleep)
// Both role bodies are the proven R3 pipelines (groups-of-4 double-buffered
// weight regs, register-prefetched x tile, m-half split inside the CTA).
// __launch_bounds__(128,5): 5 CTAs/SM guaranteed -> wave-1 capacity 740 >= 704,
// so ALL A-CTAs are resident from the start (no gating deadlock).
// ============================================================================
__global__ __launch_bounds__(128, 5)
void moe_fused_kernel(const float* __restrict__ x,
                      const float* __restrict__ gate,
                      const float* __restrict__ up,
                      const float* __restrict__ down,
                      float* __restrict__ out) {
    const int bid = blockIdx.x;
    const int tid = threadIdx.x;          // 0..127
    const int lf  = tid & 63;
    const int mh  = tid >> 6;

    __shared__ ull xs[KT * XSS];

    if (bid < NA_TOT) {
        // ==================== A role: gate+up projection ====================
        const int e  = bid / NA_PER_E;
        const int fb = bid % NA_PER_E;
        const int f  = fb * 128 + lf * 2;

        ull ag0[4], ag1[4], au0[4], au1[4];
#pragma unroll
        for (int j = 0; j < 4; j++) { ag0[j] = 0; ag1[j] = 0; au0[j] = 0; au1[j] = 0; }

        const float* xb = x + (size_t)e * MT * HH;
        float xv[8];

        // prologue: fill tile 0
#pragma unroll
        for (int i = 0; i < 4; i++) {
            int m0 = (mh * 4 + i) * 2;
            xv[2 * i]     = xb[(size_t)m0 * HH + lf];
            xv[2 * i + 1] = xb[(size_t)(m0 + 1) * HH + lf];
        }
#pragma unroll
        for (int i = 0; i < 4; i++)
            xs[lf * XSS + mh * 4 + i] = pack2(xv[2 * i], xv[2 * i + 1]);
        __syncthreads();

        const float* gp0 = gate + (size_t)e * HH * FF + f;
        const float* up0 = up   + (size_t)e * HH * FF + f;

        for (int k0 = 0; k0 < HH; k0 += KT) {
            const bool has_next = (k0 + KT < HH);
            if (has_next) {
#pragma unroll
                for (int i = 0; i < 4; i++) {
                    int m0 = (mh * 4 + i) * 2;
                    xv[2 * i]     = xb[(size_t)m0 * HH + k0 + KT + lf];
                    xv[2 * i + 1] = xb[(size_t)(m0 + 1) * HH + k0 + KT + lf];
                }
            }

            const float* gp = gp0 + (size_t)k0 * FF;
            const float* uq = up0 + (size_t)k0 * FF;

            float2 wg[2][4], wu[2][4];
#pragma unroll
            for (int j = 0; j < 4; j++) {
                wg[0][j] = *(const float2*)(gp + (size_t)j * FF);
                wu[0][j] = *(const float2*)(uq + (size_t)j * FF);
            }
#pragma unroll 2
            for (int kg = 0; kg < KT / 4; kg++) {
                const int cur = kg & 1, nxt = cur ^ 1;
                if (kg < KT / 4 - 1) {
#pragma unroll
                    for (int j = 0; j < 4; j++) {
                        wg[nxt][j] = *(const float2*)(gp + (size_t)(4 * kg + 4 + j) * FF);
                        wu[nxt][j] = *(const float2*)(uq + (size_t)(4 * kg + 4 + j) * FF);
                    }
                }
#pragma unroll
                for (int j = 0; j < 4; j++) {
                    const int k = kg * 4 + j;
                    ull g0 = dup2(wg[cur][j].x), g1 = dup2(wg[cur][j].y);
                    ull u0 = dup2(wu[cur][j].x), u1 = dup2(wu[cur][j].y);
                    const ulonglong2* xr = (const ulonglong2*)&xs[k * XSS + mh * 4];
                    ulonglong2 xa = xr[0];
                    ulonglong2 xc = xr[1];
                    ag0[0] = fma2(xa.x, g0, ag0[0]); ag1[0] = fma2(xa.x, g1, ag1[0]);
                    au0[0] = fma2(xa.x, u0, au0[0]); au1[0] = fma2(xa.x, u1, au1[0]);
                    ag0[1] = fma2(xa.y, g0, ag0[1]); ag1[1] = fma2(xa.y, g1, ag1[1]);
                    au0[1] = fma2(xa.y, u0, au0[1]); au1[1] = fma2(xa.y, u1, au1[1]);
                    ag0[2] = fma2(xc.x, g0, ag0[2]); ag1[2] = fma2(xc.x, g1, ag1[2]);
                    au0[2] = fma2(xc.x, u0, au0[2]); au1[2] = fma2(xc.x, u1, au1[2]);
                    ag0[3] = fma2(xc.y, g0, ag0[3]); ag1[3] = fma2(xc.y, g1, ag1[3]);
                    au0[3] = fma2(xc.y, u0, au0[3]); au1[3] = fma2(xc.y, u1, au1[3]);
                }
            }
            __syncthreads();
            if (has_next) {
#pragma unroll
                for (int i = 0; i < 4; i++)
                    xs[lf * XSS + mh * 4 + i] = pack2(xv[2 * i], xv[2 * i + 1]);
            }
            __syncthreads();
        }

        // epilogue: SwiGLU + store
        float* dst = g_inter + (size_t)e * MT * FF + f;
        const int mt0 = mh * 8;
#pragma unroll
        for (int j = 0; j < 4; j++) {
            float2 g0 = unpk(ag0[j]), g1 = unpk(ag1[j]);
            float2 u0 = unpk(au0[j]), u1 = unpk(au1[j]);
            const int m_lo = mt0 + 2 * j, m_hi = m_lo + 1;
            *(float2*)(dst + (size_t)m_lo * FF) =
                make_float2(silu(g0.x) * u0.x, silu(g1.x) * u1.x);
            *(float2*)(dst + (size_t)m_hi * FF) =
                make_float2(silu(g0.y) * u0.y, silu(g1.y) * u1.y);
        }

        // release: all threads fence their stores, then one arrival
        __threadfence();
        __syncthreads();
        if (tid == 0) atomicAdd(&g_done[e], 1);

    } else {
        // ==================== B role: down projection ====================
        const int b2 = bid - NA_TOT;
        const int e  = b2 / NB_PER_E;
        const int hb = b2 % NB_PER_E;
        const int h  = hb * 128 + lf * 2;

        // gate: wait for all 11 A-CTAs of this expert (acquire)
        if (tid == 0) {
            int v;
            while (true) {
                asm volatile("ld.acquire.gpu.global.b32 %0, [%1];"
                             : "=r"(v) : "l"(&g_done[e]) : "memory");
                if (v == NA_PER_E) break;
                __nanosleep(128);
            }
        }
        __syncthreads();

        ull a0[4], a1[4];
#pragma unroll
        for (int j = 0; j < 4; j++) { a0[j] = 0; a1[j] = 0; }

        const float* ib = g_inter + (size_t)e * MT * FF;
        float xv[8];

#pragma unroll
        for (int i = 0; i < 4; i++) {
            int m0 = (mh * 4 + i) * 2;
            xv[2 * i]     = ib[(size_t)m0 * FF + lf];
            xv[2 * i + 1] = ib[(size_t)(m0 + 1) * FF + lf];
        }
#pragma unroll
        for (int i = 0; i < 4; i++)
            xs[lf * XSS + mh * 4 + i] = pack2(xv[2 * i], xv[2 * i + 1]);
        __syncthreads();

        const float* dp0 = down + (size_t)e * FF * HH + h;

        for (int k0 = 0; k0 < FF; k0 += KT) {
            const bool has_next = (k0 + KT < FF);
            if (has_next) {
#pragma unroll
                for (int i = 0; i < 4; i++) {
                    int m0 = (mh * 4 + i) * 2;
                    xv[2 * i]     = ib[(size_t)m0 * FF + k0 + KT + lf];
                    xv[2 * i + 1] = ib[(size_t)(m0 + 1) * FF + k0 + KT + lf];
                }
            }

            const float* dp = dp0 + (size_t)k0 * HH;

            float2 wd[2][4];
#pragma unroll
            for (int j = 0; j < 4; j++)
                wd[0][j] = *(const float2*)(dp + (size_t)j * HH);
#pragma unroll 4
            for (int kg = 0; kg < KT / 4; kg++) {
                const int cur = kg & 1, nxt = cur ^ 1;
                if (kg < KT / 4 - 1) {
#pragma unroll
                    for (int j = 0; j < 4; j++)
                        wd[nxt][j] = *(const float2*)(dp + (size_t)(4 * kg + 4 + j) * HH);
                }
#pragma unroll
                for (int j = 0; j < 4; j++) {
                    const int k = kg * 4 + j;
                    ull w0 = dup2(wd[cur][j].x), w1 = dup2(wd[cur][j].y);
                    const ulonglong2* xr = (const ulonglong2*)&xs[k * XSS + mh * 4];
                    ulonglong2 xa = xr[0];
                    ulonglong2 xc = xr[1];
                    a0[0] = fma2(xa.x, w0, a0[0]); a1[0] = fma2(xa.x, w1, a1[0]);
                    a0[1] = fma2(xa.y, w0, a0[1]); a1[1] = fma2(xa.y, w1, a1[1]);
                    a0[2] = fma2(xc.x, w0, a0[2]); a1[2] = fma2(xc.x, w1, a1[2]);
                    a0[3] = fma2(xc.y, w0, a0[3]); a1[3] = fma2(xc.y, w1, a1[3]);
                }
            }
            __syncthreads();
            if (has_next) {
#pragma unroll
                for (int i = 0; i < 4; i++)
                    xs[lf * XSS + mh * 4 + i] = pack2(xv[2 * i], xv[2 * i + 1]);
            }
            __syncthreads();
        }

        float* ob = out + (size_t)e * MT * HH + h;
        const int mt0 = mh * 8;
#pragma unroll
        for (int j = 0; j < 4; j++) {
            float2 v0 = unpk(a0[j]);
            float2 v1 = unpk(a1[j]);
            const int m_lo = mt0 + 2 * j, m_hi = m_lo + 1;
            *(float2*)(ob + (size_t)m_lo * HH) = make_float2(v0.x, v1.x);
            *(float2*)(ob + (size_t)m_hi * HH) = make_float2(v0.y, v1.y);
        }

        // completion count; last B-CTA of this expert resets counters so the
        // next launch/replay starts from a clean (all-zero) state.
        __syncthreads();
        if (tid == 0) {
            int prev = atomicAdd(&g_bdone[e], 1);
            if (prev == NB_PER_E - 1) {
                g_done[e]  = 0;
                g_bdone[e] = 0;
            }
        }
    }
}

// ============================================================================
// Launch
// Inputs (metadata order):
//   d_in[0] = permuted_local_hidden_states [T=1024, H=2048] f32
//   d_in[1] = gate_proj [E, H, F] f32
//   d_in[2] = up_proj   [E, H, F] f32
//   d_in[3] = down_proj [E, F, H] f32
//   d_in[4] = tokens_per_expert [E] i32  (uniform 16 — unused)
// Output: [T, H] f32
// ============================================================================
extern "C" void kernel_launch(void* const* d_in, const int* in_sizes, int n_in,
                              void* d_out, int out_size) {
    const float* x    = (const float*)d_in[0];
    const float* gate = (const float*)d_in[1];
    const float* up   = (const float*)d_in[2];
    const float* down = (const float*)d_in[3];
    float* out = (float*)d_out;

    moe_fused_kernel<<<NA_TOT + NB_TOT, 128>>>(x, gate, up, down, out);
}